// round 8
// baseline (speedup 1.0000x reference)
#include <cuda_runtime.h>
#include <cuda_bf16.h>
#include <math.h>

#define SEQ_LEN 16384
#define ENC_H   2048
#define DEC_H   2048

#define R       8                       // rows per kA block
#define NBLK    (SEQ_LEN / R)           // 2048 kA blocks
#define NCHUNK  32                      // kB2 row-chunks
#define BPC     (NBLK / NCHUNK)         // 64 ctx-rows per chunk

// Scratch (device globals — no allocation allowed)
__device__ float g_v[ENC_H];
__device__ float g_ctx[NBLK * ENC_H];    // 16 MB per-block partial contexts
__device__ float g_m[NBLK];
__device__ float g_z[NBLK];
__device__ float g_p2[NCHUNK * ENC_H];   // 256 KB

// ---------------------------------------------------------------------------
// Kernel 1: v[e] = sum_d W[e,d] * dec[d]   (block per row: 2048 x 128)
// ---------------------------------------------------------------------------
__global__ __launch_bounds__(128) void k1_gemv(const float* __restrict__ W,
                                               const float* __restrict__ dec) {
    int s    = blockIdx.x;
    int t    = threadIdx.x;
    int warp = t >> 5;
    int lane = t & 31;
    const float4* row = reinterpret_cast<const float4*>(W + (size_t)s * DEC_H);
    const float4* d4  = reinterpret_cast<const float4*>(dec);

    float4 a[4], b[4];
    #pragma unroll
    for (int i = 0; i < 4; ++i) {
        a[i] = row[t + 128 * i];
        b[i] = __ldg(&d4[t + 128 * i]);
    }
    float acc = 0.0f;
    #pragma unroll
    for (int i = 0; i < 4; ++i)
        acc += a[i].x * b[i].x + a[i].y * b[i].y + a[i].z * b[i].z + a[i].w * b[i].w;
    #pragma unroll
    for (int o = 16; o > 0; o >>= 1) acc += __shfl_xor_sync(0xffffffffu, acc, o);
    __shared__ float red[4];
    if (lane == 0) red[warp] = acc;
    __syncthreads();
    if (t == 0) g_v[s] = red[0] + red[1] + red[2] + red[3];
}

// ---------------------------------------------------------------------------
// Kernel A (R6-proven): block = 256 threads owns 8 full rows; 16 independent
// LDG.128 up front, ONE reduction round, weights, accumulate. No online
// rescale, minimal syncs.
// ---------------------------------------------------------------------------
__global__ __launch_bounds__(256, 2) void kA_fused(const float* __restrict__ enc) {
    __shared__ float s_red[8][R];
    int t    = threadIdx.x;
    int warp = t >> 5;
    int lane = t & 31;
    size_t s0 = (size_t)blockIdx.x * R;

    const float4* v4 = reinterpret_cast<const float4*>(g_v);
    float4 v0 = v4[t];
    float4 v1 = v4[t + 256];

    float4 r0[R], r1[R];
    #pragma unroll
    for (int r = 0; r < R; ++r) {
        const float4* row = reinterpret_cast<const float4*>(enc + (s0 + r) * ENC_H);
        r0[r] = row[t];
        r1[r] = row[t + 256];
    }

    float d[R];
    #pragma unroll
    for (int r = 0; r < R; ++r) {
        d[r] = r0[r].x * v0.x + r0[r].y * v0.y + r0[r].z * v0.z + r0[r].w * v0.w
             + r1[r].x * v1.x + r1[r].y * v1.y + r1[r].z * v1.z + r1[r].w * v1.w;
    }
    #pragma unroll
    for (int r = 0; r < R; ++r) {
        float x = d[r];
        #pragma unroll
        for (int o = 16; o > 0; o >>= 1) x += __shfl_xor_sync(0xffffffffu, x, o);
        if (lane == 0) s_red[warp][r] = x;
    }
    __syncthreads();

    float sc[R];
    #pragma unroll
    for (int r = 0; r < R; ++r) {
        float x = 0.0f;
        #pragma unroll
        for (int w = 0; w < 8; ++w) x += s_red[w][r];
        sc[r] = x;
    }
    float m = sc[0];
    #pragma unroll
    for (int r = 1; r < R; ++r) m = fmaxf(m, sc[r]);
    float z = 0.0f;
    float w[R];
    #pragma unroll
    for (int r = 0; r < R; ++r) { w[r] = __expf(sc[r] - m); z += w[r]; }

    float4 a0 = make_float4(0.f, 0.f, 0.f, 0.f);
    float4 a1 = make_float4(0.f, 0.f, 0.f, 0.f);
    #pragma unroll
    for (int r = 0; r < R; ++r) {
        a0.x += w[r] * r0[r].x; a0.y += w[r] * r0[r].y;
        a0.z += w[r] * r0[r].z; a0.w += w[r] * r0[r].w;
        a1.x += w[r] * r1[r].x; a1.y += w[r] * r1[r].y;
        a1.z += w[r] * r1[r].z; a1.w += w[r] * r1[r].w;
    }

    float4* ctx = reinterpret_cast<float4*>(g_ctx + (size_t)blockIdx.x * ENC_H);
    ctx[t] = a0;
    ctx[t + 256] = a1;
    if (t == 0) { g_m[blockIdx.x] = m; g_z[blockIdx.x] = z; }
}

// ---------------------------------------------------------------------------
// Kernel B2: coalesced weighted partial reduction of g_ctx.
//   grid (2, 32) x 256 thr. Block (bx,by): col4s [bx*256,+256),
//   ctx-rows [by*64,+64). Redundant global max, fold e_b.
// ---------------------------------------------------------------------------
__global__ __launch_bounds__(256) void kB2_partial() {
    __shared__ float s_red[8];
    __shared__ float s_M;
    __shared__ float s_e[BPC];
    int t    = threadIdx.x;
    int warp = t >> 5;
    int lane = t & 31;
    int b0   = blockIdx.y * BPC;

    float m = -INFINITY;
    #pragma unroll
    for (int i = 0; i < NBLK / 256; ++i) m = fmaxf(m, g_m[t + 256 * i]);
    #pragma unroll
    for (int o = 16; o > 0; o >>= 1) m = fmaxf(m, __shfl_xor_sync(0xffffffffu, m, o));
    if (lane == 0) s_red[warp] = m;
    __syncthreads();
    if (t == 0) {
        float mm = s_red[0];
        #pragma unroll
        for (int wdx = 1; wdx < 8; ++wdx) mm = fmaxf(mm, s_red[wdx]);
        s_M = mm;
    }
    __syncthreads();
    if (t < BPC) s_e[t] = __expf(g_m[b0 + t] - s_M);
    __syncthreads();

    int col4 = blockIdx.x * 256 + t;          // [0, 512)
    const float4* ctx = reinterpret_cast<const float4*>(g_ctx);
    float4 acc = make_float4(0.f, 0.f, 0.f, 0.f);
    #pragma unroll 8
    for (int i = 0; i < BPC; ++i) {
        float e  = s_e[i];
        float4 c = ctx[(size_t)(b0 + i) * (ENC_H / 4) + col4];
        acc.x += e * c.x; acc.y += e * c.y; acc.z += e * c.z; acc.w += e * c.w;
    }
    reinterpret_cast<float4*>(g_p2)[blockIdx.y * (ENC_H / 4) + col4] = acc;
}

// ---------------------------------------------------------------------------
// Kernel B3: out = (sum over 32 partials) / Z.  grid 16 x 128.
//   Block bx owns 32 col4s; warp w handles row-chunks [w*8, +8); smem
//   cross-warp reduce. Only 8 L2-hot loads per thread (no long chains).
// ---------------------------------------------------------------------------
__global__ __launch_bounds__(128) void kB3_final(float* __restrict__ out) {
    __shared__ float s_red[4];
    __shared__ float s_M, s_invZ;
    __shared__ float4 s_acc[4][32];
    int t    = threadIdx.x;
    int warp = t >> 5;
    int lane = t & 31;

    // global max M
    float m = -INFINITY;
    #pragma unroll
    for (int i = 0; i < NBLK / 128; ++i) m = fmaxf(m, g_m[t + 128 * i]);
    #pragma unroll
    for (int o = 16; o > 0; o >>= 1) m = fmaxf(m, __shfl_xor_sync(0xffffffffu, m, o));
    if (lane == 0) s_red[warp] = m;
    __syncthreads();
    if (t == 0)
        s_M = fmaxf(fmaxf(s_red[0], s_red[1]), fmaxf(s_red[2], s_red[3]));
    __syncthreads();
    float M = s_M;

    // Z
    float zs = 0.0f;
    #pragma unroll
    for (int i = 0; i < NBLK / 128; ++i) {
        int b = t + 128 * i;
        zs += __expf(g_m[b] - M) * g_z[b];
    }
    #pragma unroll
    for (int o = 16; o > 0; o >>= 1) zs += __shfl_xor_sync(0xffffffffu, zs, o);
    __syncthreads();
    if (lane == 0) s_red[warp] = zs;
    __syncthreads();
    if (t == 0)
        s_invZ = 1.0f / (s_red[0] + s_red[1] + s_red[2] + s_red[3]);
    __syncthreads();

    // partial sum: warp w covers p2 rows [w*8, w*8+8), lane l -> col4
    int col4 = blockIdx.x * 32 + lane;        // [0, 512)
    const float4* p2 = reinterpret_cast<const float4*>(g_p2);
    float4 acc = make_float4(0.f, 0.f, 0.f, 0.f);
    #pragma unroll
    for (int i = 0; i < 8; ++i) {
        float4 c = p2[(size_t)(warp * 8 + i) * (ENC_H / 4) + col4];
        acc.x += c.x; acc.y += c.y; acc.z += c.z; acc.w += c.w;
    }
    s_acc[warp][lane] = acc;
    __syncthreads();
    if (warp == 0) {
        float4 a0 = s_acc[0][lane], a1 = s_acc[1][lane];
        float4 a2 = s_acc[2][lane], a3 = s_acc[3][lane];
        float inv = s_invZ;
        float4 r;
        r.x = (a0.x + a1.x + a2.x + a3.x) * inv;
        r.y = (a0.y + a1.y + a2.y + a3.y) * inv;
        r.z = (a0.z + a1.z + a2.z + a3.z) * inv;
        r.w = (a0.w + a1.w + a2.w + a3.w) * inv;
        reinterpret_cast<float4*>(out)[col4] = r;
    }
}

extern "C" void kernel_launch(void* const* d_in, const int* in_sizes, int n_in,
                              void* d_out, int out_size) {
    const float* enc = (const float*)d_in[0];   // [16384, 2048]
    const float* dec = (const float*)d_in[1];   // [1, 2048]
    const float* W   = (const float*)d_in[2];   // [2048, 2048]
    float* out = (float*)d_out;                 // [1, 2048]

    k1_gemv<<<ENC_H, 128>>>(W, dec);
    kA_fused<<<NBLK, 256>>>(enc);
    dim3 g2(2, NCHUNK);
    kB2_partial<<<g2, 256>>>();
    kB3_final<<<16, 128>>>(out);
}

// round 9
// speedup vs baseline: 1.0538x; 1.0538x over previous
#include <cuda_runtime.h>
#include <cuda_bf16.h>
#include <math.h>

#define SEQ_LEN 16384
#define ENC_H   2048
#define DEC_H   2048

#define R       8                       // rows per kA/k1 block
#define NBLK    (SEQ_LEN / R)           // 2048 kA blocks

// Scratch (device globals — no allocation allowed)
__device__ float g_v[ENC_H];
__device__ float g_ctx[NBLK * ENC_H];    // 16 MB per-block partial contexts
__device__ float g_m[NBLK];
__device__ float g_z[NBLK];

// ---------------------------------------------------------------------------
// Kernel 1: v = W @ dec, built on the kA skeleton: 256 blocks x 256 thr,
// 8 rows per block, 16 independent LDG.128 up front, ONE reduction round.
// ---------------------------------------------------------------------------
__global__ __launch_bounds__(256, 2) void k1_gemv(const float* __restrict__ W,
                                                  const float* __restrict__ dec) {
    __shared__ float s_red[8][R];
    int t    = threadIdx.x;
    int warp = t >> 5;
    int lane = t & 31;
    size_t s0 = (size_t)blockIdx.x * R;

    const float4* d4 = reinterpret_cast<const float4*>(dec);
    float4 v0 = __ldg(&d4[t]);
    float4 v1 = __ldg(&d4[t + 256]);

    float4 r0[R], r1[R];
    #pragma unroll
    for (int r = 0; r < R; ++r) {
        const float4* row = reinterpret_cast<const float4*>(W + (s0 + r) * DEC_H);
        r0[r] = row[t];
        r1[r] = row[t + 256];
    }

    #pragma unroll
    for (int r = 0; r < R; ++r) {
        float d = r0[r].x * v0.x + r0[r].y * v0.y + r0[r].z * v0.z + r0[r].w * v0.w
                + r1[r].x * v1.x + r1[r].y * v1.y + r1[r].z * v1.z + r1[r].w * v1.w;
        #pragma unroll
        for (int o = 16; o > 0; o >>= 1) d += __shfl_xor_sync(0xffffffffu, d, o);
        if (lane == 0) s_red[warp][r] = d;
    }
    __syncthreads();
    if (t < R) {
        float x = 0.0f;
        #pragma unroll
        for (int w = 0; w < 8; ++w) x += s_red[w][t];
        g_v[s0 + t] = x;
    }
}

// ---------------------------------------------------------------------------
// Kernel A (R6-proven): block = 256 threads owns 8 full rows; 16 independent
// LDG.128 up front, ONE reduction round, weights, accumulate.
// ---------------------------------------------------------------------------
__global__ __launch_bounds__(256, 2) void kA_fused(const float* __restrict__ enc) {
    __shared__ float s_red[8][R];
    int t    = threadIdx.x;
    int warp = t >> 5;
    int lane = t & 31;
    size_t s0 = (size_t)blockIdx.x * R;

    const float4* v4 = reinterpret_cast<const float4*>(g_v);
    float4 v0 = v4[t];
    float4 v1 = v4[t + 256];

    float4 r0[R], r1[R];
    #pragma unroll
    for (int r = 0; r < R; ++r) {
        const float4* row = reinterpret_cast<const float4*>(enc + (s0 + r) * ENC_H);
        r0[r] = row[t];
        r1[r] = row[t + 256];
    }

    float d[R];
    #pragma unroll
    for (int r = 0; r < R; ++r) {
        d[r] = r0[r].x * v0.x + r0[r].y * v0.y + r0[r].z * v0.z + r0[r].w * v0.w
             + r1[r].x * v1.x + r1[r].y * v1.y + r1[r].z * v1.z + r1[r].w * v1.w;
    }
    #pragma unroll
    for (int r = 0; r < R; ++r) {
        float x = d[r];
        #pragma unroll
        for (int o = 16; o > 0; o >>= 1) x += __shfl_xor_sync(0xffffffffu, x, o);
        if (lane == 0) s_red[warp][r] = x;
    }
    __syncthreads();

    float sc[R];
    #pragma unroll
    for (int r = 0; r < R; ++r) {
        float x = 0.0f;
        #pragma unroll
        for (int w = 0; w < 8; ++w) x += s_red[w][r];
        sc[r] = x;
    }
    float m = sc[0];
    #pragma unroll
    for (int r = 1; r < R; ++r) m = fmaxf(m, sc[r]);
    float z = 0.0f;
    float w[R];
    #pragma unroll
    for (int r = 0; r < R; ++r) { w[r] = __expf(sc[r] - m); z += w[r]; }

    float4 a0 = make_float4(0.f, 0.f, 0.f, 0.f);
    float4 a1 = make_float4(0.f, 0.f, 0.f, 0.f);
    #pragma unroll
    for (int r = 0; r < R; ++r) {
        a0.x += w[r] * r0[r].x; a0.y += w[r] * r0[r].y;
        a0.z += w[r] * r0[r].z; a0.w += w[r] * r0[r].w;
        a1.x += w[r] * r1[r].x; a1.y += w[r] * r1[r].y;
        a1.z += w[r] * r1[r].z; a1.w += w[r] * r1[r].w;
    }

    float4* ctx = reinterpret_cast<float4*>(g_ctx + (size_t)blockIdx.x * ENC_H);
    ctx[t] = a0;
    ctx[t + 256] = a1;
    if (t == 0) { g_m[blockIdx.x] = m; g_z[blockIdx.x] = z; }
}

// ---------------------------------------------------------------------------
// Kernel B: single-kernel combine over NBLK=2048 partials.
//   grid 128 x 256 thr. Phase 1: redundant global M, s_e[2048], invZ.
//   Phase 2: 8 warps = 4 col4s x 2 row-halves; 32 strided float4 loads/lane
//   over L2-resident ctx; shuffle reduce; smem pair-combine; write out.
// ---------------------------------------------------------------------------
__global__ __launch_bounds__(256) void kB_combine(float* __restrict__ out) {
    __shared__ float s_e[NBLK];          // 8 KB
    __shared__ float s_red[8];
    __shared__ float s_M, s_invZ;
    __shared__ float4 s_out[8];
    int t    = threadIdx.x;
    int warp = t >> 5;
    int lane = t & 31;

    // global max M over g_m[2048]
    float m = -INFINITY;
    #pragma unroll
    for (int i = 0; i < NBLK / 256; ++i) m = fmaxf(m, g_m[t + 256 * i]);
    #pragma unroll
    for (int o = 16; o > 0; o >>= 1) m = fmaxf(m, __shfl_xor_sync(0xffffffffu, m, o));
    if (lane == 0) s_red[warp] = m;
    __syncthreads();
    if (t == 0) {
        float mm = s_red[0];
        #pragma unroll
        for (int wdx = 1; wdx < 8; ++wdx) mm = fmaxf(mm, s_red[wdx]);
        s_M = mm;
    }
    __syncthreads();
    float M = s_M;

    // e_b and Z
    float zs = 0.0f;
    #pragma unroll
    for (int i = 0; i < NBLK / 256; ++i) {
        int b = t + 256 * i;
        float e = __expf(g_m[b] - M);
        s_e[b] = e;
        zs += e * g_z[b];
    }
    #pragma unroll
    for (int o = 16; o > 0; o >>= 1) zs += __shfl_xor_sync(0xffffffffu, zs, o);
    __syncthreads();
    if (lane == 0) s_red[warp] = zs;
    __syncthreads();
    if (t == 0) {
        float s = 0.0f;
        #pragma unroll
        for (int wdx = 0; wdx < 8; ++wdx) s += s_red[wdx];
        s_invZ = 1.0f / s;
    }
    __syncthreads();

    // weighted 2048-way reduction for this block's 4 col4s
    int col4 = blockIdx.x * 4 + (warp >> 1);     // [0, 512)
    int half = warp & 1;
    const float4* ctx = reinterpret_cast<const float4*>(g_ctx);
    float4 acc = make_float4(0.f, 0.f, 0.f, 0.f);
    int b0 = half * (NBLK / 2) + lane;
    #pragma unroll 8
    for (int b = b0; b < half * (NBLK / 2) + NBLK / 2; b += 32) {
        float e  = s_e[b];
        float4 c = ctx[(size_t)b * (ENC_H / 4) + col4];
        acc.x += e * c.x; acc.y += e * c.y; acc.z += e * c.z; acc.w += e * c.w;
    }
    #pragma unroll
    for (int o = 16; o > 0; o >>= 1) {
        acc.x += __shfl_xor_sync(0xffffffffu, acc.x, o);
        acc.y += __shfl_xor_sync(0xffffffffu, acc.y, o);
        acc.z += __shfl_xor_sync(0xffffffffu, acc.z, o);
        acc.w += __shfl_xor_sync(0xffffffffu, acc.w, o);
    }
    if (lane == 0) s_out[warp] = acc;
    __syncthreads();
    if (t < 4) {
        float4 a = s_out[2 * t], b = s_out[2 * t + 1];
        float inv = s_invZ;
        float4 r;
        r.x = (a.x + b.x) * inv;
        r.y = (a.y + b.y) * inv;
        r.z = (a.z + b.z) * inv;
        r.w = (a.w + b.w) * inv;
        reinterpret_cast<float4*>(out)[blockIdx.x * 4 + t] = r;
    }
}

extern "C" void kernel_launch(void* const* d_in, const int* in_sizes, int n_in,
                              void* d_out, int out_size) {
    const float* enc = (const float*)d_in[0];   // [16384, 2048]
    const float* dec = (const float*)d_in[1];   // [1, 2048]
    const float* W   = (const float*)d_in[2];   // [2048, 2048]
    float* out = (float*)d_out;                 // [1, 2048]

    k1_gemv<<<ENC_H / R, 256>>>(W, dec);
    kA_fused<<<NBLK, 256>>>(enc);
    kB_combine<<<128, 256>>>(out);
}